// round 14
// baseline (speedup 1.0000x reference)
#include <cuda_runtime.h>

#define LSEQ 512
#define CIN  256
#define HID  32
#define PAIR 64

// Transposed scratch (producer pays transpose, consumer reads coalesced)
__device__ float g_sT[HID * LSEQ];            // g_sT[c][j]
__device__ float g_tmpT[LSEQ * HID * PAIR];   // g_tmpT[i][c][k]

// ---- packed f32x2 helpers (Blackwell FFMA2) ----
static __device__ __forceinline__ void upk2(unsigned long long v, float& a, float& b) {
    asm("mov.b64 {%0, %1}, %2;" : "=f"(a), "=f"(b) : "l"(v));
}
// tied accumulator: in-place FFMA2, no result MOV
static __device__ __forceinline__ void ffma2_acc(
    unsigned long long& d, unsigned long long a, unsigned long long b) {
    asm("fma.rn.f32x2 %0, %1, %2, %0;" : "+l"(d) : "l"(a), "l"(b));
}
// direct 16B shared load into two u64 (no pack MOVs)
static __device__ __forceinline__ void lds_v2u64(
    unsigned long long& a, unsigned long long& b, unsigned int addr) {
    asm volatile("ld.shared.v2.u64 {%0, %1}, [%2];" : "=l"(a), "=l"(b) : "r"(addr));
}

// ============================================================
// K2 (byte-identical to the R10-passing version).
// ============================================================
__global__ __launch_bounds__(256) void k2_fused(
    const float* __restrict__ seq, const float* __restrict__ W1,
    const float* __restrict__ b1, const float* __restrict__ W2)
{
    extern __shared__ float sm[];
    float* region0 = sm;            // 8448 floats
    float* region1 = sm + 8448;     // 8448 floats
    __shared__ float s8[8 * HID];   // 1 KB

    int tid = threadIdx.x;
    int bx  = blockIdx.x;           // kc half: k in [bx*32, bx*32+32)
    int i0  = blockIdx.y * 8;

    {
        const float4* w1g = (const float4*)W1;
        #pragma unroll
        for (int p = 0; p < 8; p++) {
            int idx = tid + p * 256;      // 0..2047 float4s
            int h = idx >> 6, d4 = idx & 63;
            float4 v = w1g[idx];
            region0[(d4 * 4 + 0) * 33 + h] = v.x;
            region0[(d4 * 4 + 1) * 33 + h] = v.y;
            region0[(d4 * 4 + 2) * 33 + h] = v.z;
            region0[(d4 * 4 + 3) * 33 + h] = v.w;
        }
        const float4* sg = (const float4*)(seq + (size_t)i0 * CIN);
        float4* ss4 = (float4*)region1;
        #pragma unroll
        for (int p = 0; p < 2; p++) ss4[tid + p * 256] = sg[tid + p * 256];
    }
    __syncthreads();

    {
        int w = tid >> 5, h = tid & 31;
        float a0 = b1[h], a1 = 0.f, a2 = 0.f, a3 = 0.f;
        const float4* sv4 = (const float4*)(region1 + w * CIN);
        #pragma unroll 16
        for (int d4 = 0; d4 < 64; d4++) {
            float4 sv = sv4[d4];
            a0 += sv.x * region0[(d4 * 4 + 0) * 33 + h];
            a1 += sv.y * region0[(d4 * 4 + 1) * 33 + h];
            a2 += sv.z * region0[(d4 * 4 + 2) * 33 + h];
            a3 += sv.w * region0[(d4 * 4 + 3) * 33 + h];
        }
        float acc = (a0 + a1) + (a2 + a3);
        s8[tid] = acc;
        if (bx == 0) g_sT[(size_t)h * LSEQ + (i0 + w)] = acc;
    }
    __syncthreads();

    const float4* s84 = (const float4*)s8;
    #pragma unroll 1
    for (int pl = 0; pl < 4; pl++) {
        int p_abs = bx * 4 + pl;
        {
            const float4* w2g = (const float4*)(W2 + (size_t)p_abs * 256 * 32);
            #pragma unroll
            for (int q = 0; q < 8; q++) {
                int idx = tid + q * 256;
                int r = idx >> 3, f4 = idx & 7;
                float4 v = w2g[idx];
                region0[r * 33 + f4 * 4 + 0] = v.x;
                region0[r * 33 + f4 * 4 + 1] = v.y;
                region0[r * 33 + f4 * 4 + 2] = v.z;
                region0[r * 33 + f4 * 4 + 3] = v.w;
            }
        }
        __syncthreads();

        {
            int kc_local = tid;
            int c = (p_abs * 256 + tid) & 31;
            int k_half = pl * 8 + (tid >> 5);
            float w_[32];
            #pragma unroll
            for (int e = 0; e < 32; e++) w_[e] = region0[kc_local * 33 + e];
            #pragma unroll
            for (int i = 0; i < 8; i++) {
                float c0 = 0.f, c1 = 0.f, c2 = 0.f, c3 = 0.f;
                #pragma unroll
                for (int q = 0; q < 8; q++) {
                    float4 sv = s84[i * 8 + q];
                    c0 += sv.x * w_[q * 4 + 0];
                    c1 += sv.y * w_[q * 4 + 1];
                    c2 += sv.z * w_[q * 4 + 2];
                    c3 += sv.w * w_[q * 4 + 3];
                }
                region1[i * 1056 + k_half * 33 + c] = (c0 + c1) + (c2 + c3);
            }
        }
        __syncthreads();
    }

    #pragma unroll
    for (int q = 0; q < 8; q++) {
        int f = tid + q * 256;
        int r = f >> 3, f4 = f & 7;
        int i = r >> 5, c = r & 31;
        float4 v;
        v.x = region1[i * 1056 + (f4 * 4 + 0) * 33 + c];
        v.y = region1[i * 1056 + (f4 * 4 + 1) * 33 + c];
        v.z = region1[i * 1056 + (f4 * 4 + 2) * 33 + c];
        v.w = region1[i * 1056 + (f4 * 4 + 3) * 33 + c];
        *(float4*)(g_tmpT + (size_t)(i0 + i) * 2048 + c * 64 + bx * 32 + f4 * 4) = v;
    }
}

// ============================================================
// K3: R7 shape (128 threads, 8j x 8k, 4 blocks/SM) with j-packed FFMA2:
//  - acc[jp][e] = (out[j0,k], out[j1,k]) pairs, tied in-place FFMA2 (0 MOVs).
//  - s [c][j] (16 KB): ld.shared.v2.u64 yields natural (j0,j1) pairs.
//  - tmp duplicated [c][(t,t)] (16 KB): ld.shared.v2.u64 yields (t,t) pairs.
//  Inner loop per c: 6 LDS + 32 FFMA2, zero ALU packs.
// ============================================================
__global__ __launch_bounds__(128, 4) void k3_main(
    const float* __restrict__ pair_rep, const float* __restrict__ b2,
    float* __restrict__ out)
{
    __shared__ float s_sm[32 * 128];      // [c][j] 16 KB
    __shared__ float tmp_dup[32 * 128];   // [c][2k] duplicated, 16 KB

    int tid = threadIdx.x;
    int i  = blockIdx.y;
    int jt = blockIdx.x;
    int tk = tid & 7;        // k = tk*4..+3 and 32+tk*4..+3
    int tj = tid >> 3;       // j = jt*128 + tj*8 .. +7

    const float* pbase = pair_rep + (((size_t)i * 512 + (size_t)jt * 128) * 64);

    // L2 prefetch of the 32 KB pair tile
    asm volatile("prefetch.global.L2 [%0];" :: "l"(pbase + (size_t)tid * 32));
    asm volatile("prefetch.global.L2 [%0];" :: "l"(pbase + (size_t)(tid + 128) * 32));

    // staging: s direct copy [c][j]
    #pragma unroll
    for (int p = 0; p < 8; p++) {
        int idx = tid + p * 128;              // 0..1023 float4s
        int c = idx >> 5, j4 = idx & 31;
        float4 v = ((const float4*)(g_sT + c * LSEQ + jt * 128))[j4];
        ((float4*)(s_sm + c * 128))[j4] = v;
    }
    // staging: tmp duplicated [c][2k]
    #pragma unroll
    for (int p = 0; p < 4; p++) {
        int idx = tid + p * 128;              // 0..511 float4s; idx = c*16 + k4
        int c = idx >> 4, k4 = idx & 15;
        float4 v = ((const float4*)(g_tmpT + (size_t)i * 2048))[idx];
        float2* d = (float2*)(tmp_dup + c * 128 + k4 * 8);
        d[0] = make_float2(v.x, v.x);
        d[1] = make_float2(v.y, v.y);
        d[2] = make_float2(v.z, v.z);
        d[3] = make_float2(v.w, v.w);
    }
    const float4* b24 = (const float4*)b2;
    float4 bz0 = b24[tk], bz1 = b24[8 + tk];
    __syncthreads();

    // acc[jp][e]: jp = j-pair (j = tj*8 + jp*2 + {0,1}); e<4 -> k=tk*4+e, e>=4 -> k=32+tk*4+(e-4)
    unsigned long long acc[4][8];
    #pragma unroll
    for (int a = 0; a < 4; a++)
        #pragma unroll
        for (int b = 0; b < 8; b++) acc[a][b] = 0ull;

    unsigned int s_base = (unsigned int)__cvta_generic_to_shared(s_sm) + tj * 32;
    unsigned int t_base = (unsigned int)__cvta_generic_to_shared(tmp_dup) + tk * 32;

    #pragma unroll 4
    for (int c = 0; c < 32; c++) {
        unsigned long long sp[4];
        lds_v2u64(sp[0], sp[1], s_base + c * 512);        // (j0,j1),(j2,j3)
        lds_v2u64(sp[2], sp[3], s_base + c * 512 + 16);   // (j4,j5),(j6,j7)
        unsigned long long t[8];
        lds_v2u64(t[0], t[1], t_base + c * 512);          // (k,k) k=tk*4,tk*4+1
        lds_v2u64(t[2], t[3], t_base + c * 512 + 16);     // k=tk*4+2,+3
        lds_v2u64(t[4], t[5], t_base + c * 512 + 256);    // k=32+tk*4,+1
        lds_v2u64(t[6], t[7], t_base + c * 512 + 272);    // k=32+tk*4+2,+3
        #pragma unroll
        for (int jp = 0; jp < 4; jp++) {
            #pragma unroll
            for (int e = 0; e < 8; e++) ffma2_acc(acc[jp][e], sp[jp], t[e]);
        }
    }

    // epilogue: per j-pair, unpack 8 u64 -> two rows of 8 k floats;
    // direct pair LDG (L2-warm) + add + streaming stores.
    #pragma unroll
    for (int jp = 0; jp < 4; jp++) {
        float lo[8], hi[8];
        #pragma unroll
        for (int e = 0; e < 8; e++) upk2(acc[jp][e], lo[e], hi[e]);

        int j0 = tj * 8 + jp * 2;
        #pragma unroll
        for (int half = 0; half < 2; half++) {
            float* r = half ? hi : lo;
            int jloc = j0 + half;
            const float4* pp = (const float4*)(pbase + (size_t)jloc * 64);
            float4 p0 = __ldg(pp + tk);
            float4 p1 = __ldg(pp + 8 + tk);
            float4 o0 = make_float4(r[0] + p0.x + bz0.x, r[1] + p0.y + bz0.y,
                                    r[2] + p0.z + bz0.z, r[3] + p0.w + bz0.w);
            float4 o1 = make_float4(r[4] + p1.x + bz1.x, r[5] + p1.y + bz1.y,
                                    r[6] + p1.z + bz1.z, r[7] + p1.w + bz1.w);
            size_t base = (((size_t)i * 512 + (size_t)(jt * 128 + jloc)) * 64);
            float4* op = (float4*)(out + base);
            __stcs(op + tk, o0);
            __stcs(op + 8 + tk, o1);
        }
    }
}

// ============================================================
// Launch. Inputs (metadata order): seq, pair_rep, W1, b1, W2, b2.
// ============================================================
extern "C" void kernel_launch(void* const* d_in, const int* in_sizes, int n_in,
                              void* d_out, int out_size)
{
    const float* seq  = (const float*)d_in[0];
    const float* pair = (const float*)d_in[1];
    const float* W1   = (const float*)d_in[2];
    const float* b1   = (const float*)d_in[3];
    const float* W2   = (const float*)d_in[4];
    const float* b2   = (const float*)d_in[5];
    float* out = (float*)d_out;

    const int k2_smem = (8448 + 8448) * 4;   // 67.6 KB
    cudaFuncSetAttribute(k2_fused, cudaFuncAttributeMaxDynamicSharedMemorySize, k2_smem);

    dim3 g2(2, 64);
    k2_fused<<<g2, 256, k2_smem>>>(seq, W1, b1, W2);
    dim3 g3(4, LSEQ);
    k3_main<<<g3, 128>>>(pair, b2, out);
}

// round 15
// speedup vs baseline: 1.2856x; 1.2856x over previous
#include <cuda_runtime.h>

#define LSEQ 512
#define CIN  256
#define HID  32
#define PAIR 64

// Transposed scratch (producer pays transpose, consumer reads coalesced)
__device__ float g_sT[HID * LSEQ];            // g_sT[c][j]
__device__ float g_tmpT[LSEQ * HID * PAIR];   // g_tmpT[i][c][k]

// ============================================================
// K2 (byte-identical to the R10-passing version).
// ============================================================
__global__ __launch_bounds__(256) void k2_fused(
    const float* __restrict__ seq, const float* __restrict__ W1,
    const float* __restrict__ b1, const float* __restrict__ W2)
{
    extern __shared__ float sm[];
    float* region0 = sm;            // 8448 floats
    float* region1 = sm + 8448;     // 8448 floats
    __shared__ float s8[8 * HID];   // 1 KB

    int tid = threadIdx.x;
    int bx  = blockIdx.x;           // kc half: k in [bx*32, bx*32+32)
    int i0  = blockIdx.y * 8;

    {
        const float4* w1g = (const float4*)W1;
        #pragma unroll
        for (int p = 0; p < 8; p++) {
            int idx = tid + p * 256;      // 0..2047 float4s
            int h = idx >> 6, d4 = idx & 63;
            float4 v = w1g[idx];
            region0[(d4 * 4 + 0) * 33 + h] = v.x;
            region0[(d4 * 4 + 1) * 33 + h] = v.y;
            region0[(d4 * 4 + 2) * 33 + h] = v.z;
            region0[(d4 * 4 + 3) * 33 + h] = v.w;
        }
        const float4* sg = (const float4*)(seq + (size_t)i0 * CIN);
        float4* ss4 = (float4*)region1;
        #pragma unroll
        for (int p = 0; p < 2; p++) ss4[tid + p * 256] = sg[tid + p * 256];
    }
    __syncthreads();

    {
        int w = tid >> 5, h = tid & 31;
        float a0 = b1[h], a1 = 0.f, a2 = 0.f, a3 = 0.f;
        const float4* sv4 = (const float4*)(region1 + w * CIN);
        #pragma unroll 16
        for (int d4 = 0; d4 < 64; d4++) {
            float4 sv = sv4[d4];
            a0 += sv.x * region0[(d4 * 4 + 0) * 33 + h];
            a1 += sv.y * region0[(d4 * 4 + 1) * 33 + h];
            a2 += sv.z * region0[(d4 * 4 + 2) * 33 + h];
            a3 += sv.w * region0[(d4 * 4 + 3) * 33 + h];
        }
        float acc = (a0 + a1) + (a2 + a3);
        s8[tid] = acc;
        if (bx == 0) g_sT[(size_t)h * LSEQ + (i0 + w)] = acc;
    }
    __syncthreads();

    const float4* s84 = (const float4*)s8;
    #pragma unroll 1
    for (int pl = 0; pl < 4; pl++) {
        int p_abs = bx * 4 + pl;
        {
            const float4* w2g = (const float4*)(W2 + (size_t)p_abs * 256 * 32);
            #pragma unroll
            for (int q = 0; q < 8; q++) {
                int idx = tid + q * 256;
                int r = idx >> 3, f4 = idx & 7;
                float4 v = w2g[idx];
                region0[r * 33 + f4 * 4 + 0] = v.x;
                region0[r * 33 + f4 * 4 + 1] = v.y;
                region0[r * 33 + f4 * 4 + 2] = v.z;
                region0[r * 33 + f4 * 4 + 3] = v.w;
            }
        }
        __syncthreads();

        {
            int kc_local = tid;
            int c = (p_abs * 256 + tid) & 31;
            int k_half = pl * 8 + (tid >> 5);
            float w_[32];
            #pragma unroll
            for (int e = 0; e < 32; e++) w_[e] = region0[kc_local * 33 + e];
            #pragma unroll
            for (int i = 0; i < 8; i++) {
                float c0 = 0.f, c1 = 0.f, c2 = 0.f, c3 = 0.f;
                #pragma unroll
                for (int q = 0; q < 8; q++) {
                    float4 sv = s84[i * 8 + q];
                    c0 += sv.x * w_[q * 4 + 0];
                    c1 += sv.y * w_[q * 4 + 1];
                    c2 += sv.z * w_[q * 4 + 2];
                    c3 += sv.w * w_[q * 4 + 3];
                }
                region1[i * 1056 + k_half * 33 + c] = (c0 + c1) + (c2 + c3);
            }
        }
        __syncthreads();
    }

    #pragma unroll
    for (int q = 0; q < 8; q++) {
        int f = tid + q * 256;
        int r = f >> 3, f4 = f & 7;
        int i = r >> 5, c = r & 31;
        float4 v;
        v.x = region1[i * 1056 + (f4 * 4 + 0) * 33 + c];
        v.y = region1[i * 1056 + (f4 * 4 + 1) * 33 + c];
        v.z = region1[i * 1056 + (f4 * 4 + 2) * 33 + c];
        v.w = region1[i * 1056 + (f4 * 4 + 3) * 33 + c];
        *(float4*)(g_tmpT + (size_t)(i0 + i) * 2048 + c * 64 + bx * 32 + f4 * 4) = v;
    }
}

// ============================================================
// K3: R7 memory structure, SCALAR FFMA core (no f32x2, no u64 pairs).
// grid (4, 512): by = i, bx = jt (j-tile 128). 128 threads, 24 KB smem,
// __launch_bounds__(128,5) -> 20 warps/SM.
// Per c: 4 conflict-free LDS.128 + 64 scalar FFMA, zero ALU MOVs.
// Epilogue: L2-prefetched direct pair LDG + add + streaming STG.
// ============================================================
__global__ __launch_bounds__(128, 5) void k3_main(
    const float* __restrict__ pair_rep, const float* __restrict__ b2,
    float* __restrict__ out)
{
    __shared__ float s_sm[32 * 128];    // [c][j] 16 KB
    __shared__ float tmp_sm[32 * 64];   // [c][k]  8 KB

    int tid = threadIdx.x;
    int i  = blockIdx.y;
    int jt = blockIdx.x;
    int tk = tid & 7;        // k = tk*4..+3 and 32+tk*4..+3
    int tj = tid >> 3;       // j = jt*128 + tj*8 .. +7

    const float* pbase = pair_rep + (((size_t)i * 512 + (size_t)jt * 128) * 64);

    // L2 prefetch of the 32 KB pair tile (256 lines, 2/thread)
    asm volatile("prefetch.global.L2 [%0];" :: "l"(pbase + (size_t)tid * 32));
    asm volatile("prefetch.global.L2 [%0];" :: "l"(pbase + (size_t)(tid + 128) * 32));

    // staging: coalesced LDG + direct STS
    #pragma unroll
    for (int p = 0; p < 8; p++) {
        int idx = tid + p * 128;              // 0..1023 float4s
        int c = idx >> 5, j4 = idx & 31;
        float4 v = ((const float4*)(g_sT + c * LSEQ + jt * 128))[j4];
        ((float4*)(s_sm + c * 128))[j4] = v;
    }
    #pragma unroll
    for (int p = 0; p < 4; p++) {
        int idx = tid + p * 128;              // 0..511 float4s
        float4 v = ((const float4*)(g_tmpT + (size_t)i * 2048))[idx];
        ((float4*)tmp_sm)[idx] = v;
    }
    const float4* b24 = (const float4*)b2;
    float4 bz0 = b24[tk], bz1 = b24[8 + tk];
    __syncthreads();

    // 8j x 8k scalar accumulator tile
    float acc[8][8];
    #pragma unroll
    for (int a = 0; a < 8; a++)
        #pragma unroll
        for (int b = 0; b < 8; b++) acc[a][b] = 0.f;

    const float4* t4 = (const float4*)tmp_sm;   // row = 16 float4
    const float4* s4 = (const float4*)s_sm;     // row = 32 float4

    #pragma unroll 4
    for (int c = 0; c < 32; c++) {
        float4 ta = t4[c * 16 + tk];            // k = tk*4..+3
        float4 tb = t4[c * 16 + 8 + tk];        // k = 32+tk*4..+3
        float tv[8] = {ta.x, ta.y, ta.z, ta.w, tb.x, tb.y, tb.z, tb.w};
        float4 sa = s4[c * 32 + tj * 2];
        float4 sb = s4[c * 32 + tj * 2 + 1];
        float sv[8] = {sa.x, sa.y, sa.z, sa.w, sb.x, sb.y, sb.z, sb.w};
        #pragma unroll
        for (int jj = 0; jj < 8; jj++)
            #pragma unroll
            for (int kk = 0; kk < 8; kk++)
                acc[jj][kk] += sv[jj] * tv[kk];
    }

    // epilogue: direct pair LDG (L2-warm) + add + streaming stores
    #pragma unroll
    for (int jj = 0; jj < 8; jj++) {
        int jloc = tj * 8 + jj;
        const float4* pp = (const float4*)(pbase + (size_t)jloc * 64);
        float4 p0 = __ldg(pp + tk);
        float4 p1 = __ldg(pp + 8 + tk);
        float4 o0 = make_float4(acc[jj][0] + p0.x + bz0.x, acc[jj][1] + p0.y + bz0.y,
                                acc[jj][2] + p0.z + bz0.z, acc[jj][3] + p0.w + bz0.w);
        float4 o1 = make_float4(acc[jj][4] + p1.x + bz1.x, acc[jj][5] + p1.y + bz1.y,
                                acc[jj][6] + p1.z + bz1.z, acc[jj][7] + p1.w + bz1.w);
        size_t base = (((size_t)i * 512 + (size_t)(jt * 128 + jloc)) * 64);
        float4* op = (float4*)(out + base);
        __stcs(op + tk, o0);
        __stcs(op + 8 + tk, o1);
    }
}

// ============================================================
// Launch. Inputs (metadata order): seq, pair_rep, W1, b1, W2, b2.
// ============================================================
extern "C" void kernel_launch(void* const* d_in, const int* in_sizes, int n_in,
                              void* d_out, int out_size)
{
    const float* seq  = (const float*)d_in[0];
    const float* pair = (const float*)d_in[1];
    const float* W1   = (const float*)d_in[2];
    const float* b1   = (const float*)d_in[3];
    const float* W2   = (const float*)d_in[4];
    const float* b2   = (const float*)d_in[5];
    float* out = (float*)d_out;

    const int k2_smem = (8448 + 8448) * 4;   // 67.6 KB
    cudaFuncSetAttribute(k2_fused, cudaFuncAttributeMaxDynamicSharedMemorySize, k2_smem);

    dim3 g2(2, 64);
    k2_fused<<<g2, 256, k2_smem>>>(seq, W1, b1, W2);
    dim3 g3(4, LSEQ);
    k3_main<<<g3, 128>>>(pair, b2, out);
}